// round 1
// baseline (speedup 1.0000x reference)
#include <cuda_runtime.h>

#define NTOK 22016   // 512*43
#define NB   512
#define TT   43
#define HD   128
#define DK   96
#define DKP  97      // padded pitch for smem (bank-conflict-free)
#define SSP  44      // scores pitch
#define DFF  2048
#define OUTV 8000
#define LNEPS 1e-5f

// ---------------- scratch (device globals; no runtime allocation) ----------------
__device__ float g_x0 [NTOK * HD];
__device__ float g_q1 [NTOK * DK];
__device__ float g_k1 [NTOK * DK];
__device__ float g_v1 [NTOK * DK];
__device__ float g_q2 [NTOK * DK];
__device__ float g_k2 [NTOK * DK];
__device__ float g_v2 [NTOK * DK];
__device__ float g_h12[NTOK * 2 * DK];
__device__ float g_mho[NTOK * HD];
__device__ float g_x1 [NTOK * HD];
__device__ float g_ffh[NTOK * DFF];
__device__ float g_ff2[NTOK * HD];
__device__ float g_x2 [NTOK * HD];

// ---------------- embed: x0 = emb[inputs] + pos_emb ----------------
__global__ void embed_kernel(const int* __restrict__ inputs,
                             const float* __restrict__ emb,
                             const float* __restrict__ pos,
                             float* __restrict__ x0) {
    int idx = blockIdx.x * blockDim.x + threadIdx.x;   // over NTOK*32 float4
    if (idx >= NTOK * (HD / 4)) return;
    int tok = idx >> 5;          // /32
    int c   = idx & 31;
    int t   = tok % TT;
    int w   = inputs[tok];
    float4 e = ((const float4*)emb)[(long)w * 32 + c];
    float4 p = ((const float4*)pos)[t * 32 + c];
    float4 r;
    r.x = e.x + p.x; r.y = e.y + p.y; r.z = e.z + p.z; r.w = e.w + p.w;
    ((float4*)x0)[idx] = r;
}

// ---------------- generic linear: Y[M,O] = X[M,K] @ W[O,K]^T + b ----------------
// BM=BN=64, BK=16, 256 threads, 4x4 per thread. M % 64 == 0 assumed; O guarded.
template<bool RELU>
__global__ __launch_bounds__(256)
void linear_kernel(const float* __restrict__ X, const float* __restrict__ W,
                   const float* __restrict__ B, float* __restrict__ Y,
                   int M, int K, int O) {
    __shared__ float As[16][64];
    __shared__ float Bs[16][64];
    int tid = threadIdx.x;
    int m0 = blockIdx.y * 64;
    int n0 = blockIdx.x * 64;
    int lr = tid >> 2;       // 0..63
    int lc = tid & 3;        // 0..3 (float4 within 16-wide k chunk)
    int tx = tid & 15;
    int ty = tid >> 4;

    float acc[4][4];
#pragma unroll
    for (int i = 0; i < 4; i++)
#pragma unroll
        for (int j = 0; j < 4; j++) acc[i][j] = 0.f;

    for (int kk = 0; kk < K; kk += 16) {
        float4 a = *(const float4*)&X[(long)(m0 + lr) * K + kk + lc * 4];
        As[lc * 4 + 0][lr] = a.x;
        As[lc * 4 + 1][lr] = a.y;
        As[lc * 4 + 2][lr] = a.z;
        As[lc * 4 + 3][lr] = a.w;
        int wr = n0 + lr;
        float4 w4 = make_float4(0.f, 0.f, 0.f, 0.f);
        if (wr < O) w4 = *(const float4*)&W[(long)wr * K + kk + lc * 4];
        Bs[lc * 4 + 0][lr] = w4.x;
        Bs[lc * 4 + 1][lr] = w4.y;
        Bs[lc * 4 + 2][lr] = w4.z;
        Bs[lc * 4 + 3][lr] = w4.w;
        __syncthreads();
#pragma unroll
        for (int k = 0; k < 16; k++) {
            float4 a4 = *(const float4*)&As[k][ty * 4];
            float4 b4 = *(const float4*)&Bs[k][tx * 4];
            float av[4] = {a4.x, a4.y, a4.z, a4.w};
            float bv[4] = {b4.x, b4.y, b4.z, b4.w};
#pragma unroll
            for (int i = 0; i < 4; i++)
#pragma unroll
                for (int j = 0; j < 4; j++)
                    acc[i][j] += av[i] * bv[j];
        }
        __syncthreads();
    }

#pragma unroll
    for (int i = 0; i < 4; i++) {
        long row = m0 + ty * 4 + i;
#pragma unroll
        for (int j = 0; j < 4; j++) {
            int col = n0 + tx * 4 + j;
            if (col < O) {
                float r = acc[i][j] + B[col];
                if (RELU) r = fmaxf(r, 0.f);
                Y[row * O + col] = r;
            }
        }
    }
}

// ---------------- per-batch attention head ----------------
// one block per batch n; q,k,v are [NTOK, DK] for this head.
__global__ __launch_bounds__(256)
void attn_kernel(const float* __restrict__ q, const float* __restrict__ k,
                 const float* __restrict__ v, float* __restrict__ h12, int head) {
    __shared__ float sq[TT * DKP];   // q, later reused for v
    __shared__ float sk[TT * DKP];
    __shared__ float ss[TT * SSP];
    int n = blockIdx.x;
    int tid = threadIdx.x;
    long base = (long)n * TT * DK;

    // load q,k (padded pitch)
    for (int i = tid; i < TT * DK / 4; i += 256) {
        float4 a = ((const float4*)(q + base))[i];
        float4 b = ((const float4*)(k + base))[i];
        int e = i * 4;
        int t = e / DK, d = e % DK;
        sq[t * DKP + d + 0] = a.x; sq[t * DKP + d + 1] = a.y;
        sq[t * DKP + d + 2] = a.z; sq[t * DKP + d + 3] = a.w;
        sk[t * DKP + d + 0] = b.x; sk[t * DKP + d + 1] = b.y;
        sk[t * DKP + d + 2] = b.z; sk[t * DKP + d + 3] = b.w;
    }
    __syncthreads();

    const float scale = rsqrtf((float)DK);
    for (int idx = tid; idx < TT * TT; idx += 256) {
        int t = idx / TT, s = idx % TT;
        float acc = 0.f;
#pragma unroll 8
        for (int d = 0; d < DK; d++) acc += sq[t * DKP + d] * sk[s * DKP + d];
        ss[t * SSP + s] = acc * scale;
    }
    __syncthreads();

    // overwrite sq with v (q no longer needed)
    for (int i = tid; i < TT * DK / 4; i += 256) {
        float4 a = ((const float4*)(v + base))[i];
        int e = i * 4;
        int t = e / DK, d = e % DK;
        sq[t * DKP + d + 0] = a.x; sq[t * DKP + d + 1] = a.y;
        sq[t * DKP + d + 2] = a.z; sq[t * DKP + d + 3] = a.w;
    }
    // softmax: one warp per score row
    int wid = tid >> 5, lane = tid & 31;
    for (int t = wid; t < TT; t += 8) {
        float m = -1e30f;
        for (int s = lane; s < TT; s += 32) m = fmaxf(m, ss[t * SSP + s]);
#pragma unroll
        for (int o = 16; o; o >>= 1) m = fmaxf(m, __shfl_xor_sync(0xffffffffu, m, o));
        float sum = 0.f;
        for (int s = lane; s < TT; s += 32) {
            float e = __expf(ss[t * SSP + s] - m);
            ss[t * SSP + s] = e;
            sum += e;
        }
#pragma unroll
        for (int o = 16; o; o >>= 1) sum += __shfl_xor_sync(0xffffffffu, sum, o);
        float inv = 1.f / sum;
        for (int s = lane; s < TT; s += 32) ss[t * SSP + s] *= inv;
    }
    __syncthreads();

    // out = attn @ v, write into concat buffer [NTOK, 192]
    for (int idx = tid; idx < TT * DK; idx += 256) {
        int t = idx / DK, d = idx % DK;
        float acc = 0.f;
#pragma unroll 43
        for (int s = 0; s < TT; s++) acc += ss[t * SSP + s] * sq[s * DKP + d];
        h12[(long)(n * TT + t) * (2 * DK) + head * DK + d] = acc;
    }
}

// ---------------- add residual + LayerNorm (one block per token row) ----------------
__global__ __launch_bounds__(128)
void add_ln_kernel(const float* __restrict__ y, const float* __restrict__ r,
                   const float* __restrict__ g, const float* __restrict__ b,
                   float* __restrict__ o) {
    long row = blockIdx.x;
    int h = threadIdx.x;
    __shared__ float red[8];
    float v = y[row * HD + h] + r[row * HD + h];
    float s = v;
#pragma unroll
    for (int off = 16; off; off >>= 1) s += __shfl_xor_sync(0xffffffffu, s, off);
    int wid = h >> 5, lane = h & 31;
    if (!lane) red[wid] = s;
    __syncthreads();
    float mean = (red[0] + red[1] + red[2] + red[3]) * (1.f / HD);
    float d = v - mean;
    float s2 = d * d;
#pragma unroll
    for (int off = 16; off; off >>= 1) s2 += __shfl_xor_sync(0xffffffffu, s2, off);
    if (!lane) red[4 + wid] = s2;
    __syncthreads();
    float var = (red[4] + red[5] + red[6] + red[7]) * (1.f / HD);
    o[row * HD + h] = d * rsqrtf(var + LNEPS) * g[h] + b[h];
}

// ---------------- host launch ----------------
extern "C" void kernel_launch(void* const* d_in, const int* in_sizes, int n_in,
                              void* d_out, int out_size) {
    const int*   inputs = (const int*)  d_in[0];
    const float* emb    = (const float*)d_in[1];
    const float* pos    = (const float*)d_in[2];
    const float* Wk1 = (const float*)d_in[3],  *bk1 = (const float*)d_in[4];
    const float* Wv1 = (const float*)d_in[5],  *bv1 = (const float*)d_in[6];
    const float* Wq1 = (const float*)d_in[7],  *bq1 = (const float*)d_in[8];
    const float* Wk2 = (const float*)d_in[9],  *bk2 = (const float*)d_in[10];
    const float* Wv2 = (const float*)d_in[11], *bv2 = (const float*)d_in[12];
    const float* Wq2 = (const float*)d_in[13], *bq2 = (const float*)d_in[14];
    const float* Wproj = (const float*)d_in[15], *bproj = (const float*)d_in[16];
    const float* gmh   = (const float*)d_in[17], *bmh   = (const float*)d_in[18];
    const float* Wff1  = (const float*)d_in[19], *bff1  = (const float*)d_in[20];
    const float* Wff2  = (const float*)d_in[21], *bff2  = (const float*)d_in[22];
    const float* gff   = (const float*)d_in[23], *bffb  = (const float*)d_in[24];
    const float* Wfin  = (const float*)d_in[25], *bfin  = (const float*)d_in[26];
    float* out = (float*)d_out;

    float *x0, *q1, *k1, *v1, *q2, *k2, *v2, *h12, *mho, *x1, *ffh, *ff2, *x2;
    cudaGetSymbolAddress((void**)&x0,  g_x0);
    cudaGetSymbolAddress((void**)&q1,  g_q1);
    cudaGetSymbolAddress((void**)&k1,  g_k1);
    cudaGetSymbolAddress((void**)&v1,  g_v1);
    cudaGetSymbolAddress((void**)&q2,  g_q2);
    cudaGetSymbolAddress((void**)&k2,  g_k2);
    cudaGetSymbolAddress((void**)&v2,  g_v2);
    cudaGetSymbolAddress((void**)&h12, g_h12);
    cudaGetSymbolAddress((void**)&mho, g_mho);
    cudaGetSymbolAddress((void**)&x1,  g_x1);
    cudaGetSymbolAddress((void**)&ffh, g_ffh);
    cudaGetSymbolAddress((void**)&ff2, g_ff2);
    cudaGetSymbolAddress((void**)&x2,  g_x2);

    const int MB = NTOK / 64;  // 344

    embed_kernel<<<(NTOK * 32 + 255) / 256, 256>>>(inputs, emb, pos, x0);

    dim3 gqkv(2, MB);  // O=96 -> 2 col tiles
    linear_kernel<false><<<gqkv, 256>>>(x0, Wq1, bq1, q1, NTOK, HD, DK);
    linear_kernel<false><<<gqkv, 256>>>(x0, Wk1, bk1, k1, NTOK, HD, DK);
    linear_kernel<false><<<gqkv, 256>>>(x0, Wv1, bv1, v1, NTOK, HD, DK);
    linear_kernel<false><<<gqkv, 256>>>(x0, Wq2, bq2, q2, NTOK, HD, DK);
    linear_kernel<false><<<gqkv, 256>>>(x0, Wk2, bk2, k2, NTOK, HD, DK);
    linear_kernel<false><<<gqkv, 256>>>(x0, Wv2, bv2, v2, NTOK, HD, DK);

    attn_kernel<<<NB, 256>>>(q1, k1, v1, h12, 0);
    attn_kernel<<<NB, 256>>>(q2, k2, v2, h12, 1);

    linear_kernel<false><<<dim3(2, MB), 256>>>(h12, Wproj, bproj, mho, NTOK, 2 * DK, HD);
    add_ln_kernel<<<NTOK, 128>>>(mho, x0, gmh, bmh, x1);

    linear_kernel<true ><<<dim3(DFF / 64, MB), 256>>>(x1, Wff1, bff1, ffh, NTOK, HD, DFF);
    linear_kernel<false><<<dim3(2, MB), 256>>>(ffh, Wff2, bff2, ff2, NTOK, DFF, HD);
    add_ln_kernel<<<NTOK, 128>>>(ff2, x1, gff, bffb, x2);

    linear_kernel<false><<<dim3(OUTV / 64, MB), 256>>>(x2, Wfin, bfin, out, NTOK, HD, OUTV);
}

// round 2
// speedup vs baseline: 1.7115x; 1.7115x over previous
#include <cuda_runtime.h>
#include <cuda_bf16.h>

typedef __nv_bfloat16 bf16;

#define NTOK 22016   // 512*43
#define NB   512
#define TT   43
#define HD   128
#define DK   96
#define DKP  97
#define SSP  44
#define DFF  2048
#define OUTV 8000
#define LNEPS 1e-5f

// weight offsets inside packed bf16 weight scratch
#define OFF_K1   0
#define OFF_V1   12288
#define OFF_Q1   24576
#define OFF_K2   36864
#define OFF_V2   49152
#define OFF_Q2   61440
#define OFF_PROJ 73728
#define OFF_FF1  98304
#define OFF_FF2  360448
#define OFF_FIN  622592
#define WTOT     1646592

// ---------------- scratch (device globals; no runtime allocation) ----------------
__device__ float g_x0 [NTOK * HD];
__device__ bf16  g_x0h[NTOK * HD];
__device__ bf16  g_x0l[NTOK * HD];
__device__ float g_q1 [NTOK * DK];
__device__ float g_k1 [NTOK * DK];
__device__ float g_v1 [NTOK * DK];
__device__ float g_q2 [NTOK * DK];
__device__ float g_k2 [NTOK * DK];
__device__ float g_v2 [NTOK * DK];
__device__ bf16  g_h12h[NTOK * 2 * DK];
__device__ bf16  g_h12l[NTOK * 2 * DK];
__device__ float g_mho[NTOK * HD];
__device__ float g_x1 [NTOK * HD];
__device__ bf16  g_x1h[NTOK * HD];
__device__ bf16  g_x1l[NTOK * HD];
__device__ bf16  g_ffhh[NTOK * DFF];
__device__ bf16  g_ffhl[NTOK * DFF];
__device__ float g_ff2[NTOK * HD];
__device__ float g_x2 [NTOK * HD];
__device__ bf16  g_x2h[NTOK * HD];
__device__ bf16  g_x2l[NTOK * HD];
__device__ bf16  g_wh[WTOT];
__device__ bf16  g_wl[WTOT];

__device__ __forceinline__ void split_store(float v, bf16* h, bf16* l, size_t i) {
    bf16 hv = __float2bfloat16(v);
    h[i] = hv;
    l[i] = __float2bfloat16(v - __bfloat162float(hv));
}

// ---------------- embed: x0 = emb[inputs] + pos_emb (fp32 + bf16 pair) ----------------
__global__ void embed_kernel(const int* __restrict__ inputs,
                             const float* __restrict__ emb,
                             const float* __restrict__ pos,
                             float* __restrict__ x0,
                             bf16* __restrict__ x0h, bf16* __restrict__ x0l) {
    int idx = blockIdx.x * blockDim.x + threadIdx.x;   // over NTOK*32 float4
    if (idx >= NTOK * (HD / 4)) return;
    int tok = idx >> 5;
    int c   = idx & 31;
    int t   = tok % TT;
    int w   = inputs[tok];
    float4 e = ((const float4*)emb)[(long)w * 32 + c];
    float4 p = ((const float4*)pos)[t * 32 + c];
    float4 r;
    r.x = e.x + p.x; r.y = e.y + p.y; r.z = e.z + p.z; r.w = e.w + p.w;
    ((float4*)x0)[idx] = r;
    size_t b = (size_t)idx * 4;
    split_store(r.x, x0h, x0l, b + 0);
    split_store(r.y, x0h, x0l, b + 1);
    split_store(r.z, x0h, x0l, b + 2);
    split_store(r.w, x0h, x0l, b + 3);
}

// ---------------- weight fp32 -> bf16 hi/lo ----------------
__global__ void convert_kernel(const float* __restrict__ x,
                               bf16* __restrict__ h, bf16* __restrict__ l, int n) {
    int i = blockIdx.x * blockDim.x + threadIdx.x;
    if (i < n) {
        float v = x[i];
        bf16 hv = __float2bfloat16(v);
        h[i] = hv;
        l[i] = __float2bfloat16(v - __bfloat162float(hv));
    }
}

// ---------------- tensor-core GEMM: Y[M,O] = X[M,K] @ W[O,K]^T + b ----------------
// X,W given as bf16 (hi,lo) pairs; fp32 accumulate of hi*hi + hi*lo + lo*hi.
// BM=128, BN=64, BK=32, 256 threads, warp tile 32x32 (m16n8k16).
// OUT_MODE 0: fp32 out.  OUT_MODE 1: relu + bf16 hi/lo out.
__device__ __forceinline__ unsigned smem_u32(const void* p) {
    return (unsigned)__cvta_generic_to_shared(p);
}

#define LDMX4(R, ADDR) \
    asm volatile("ldmatrix.sync.aligned.m8n8.x4.shared.b16 {%0,%1,%2,%3},[%4];\n" \
        : "=r"((R)[0]), "=r"((R)[1]), "=r"((R)[2]), "=r"((R)[3]) : "r"(ADDR))

#define MMA16816(C, A, B0, B1) \
    asm volatile("mma.sync.aligned.m16n8k16.row.col.f32.bf16.bf16.f32 " \
        "{%0,%1,%2,%3},{%4,%5,%6,%7},{%8,%9},{%0,%1,%2,%3};\n" \
        : "+f"((C)[0]), "+f"((C)[1]), "+f"((C)[2]), "+f"((C)[3]) \
        : "r"((A)[0]), "r"((A)[1]), "r"((A)[2]), "r"((A)[3]), "r"(B0), "r"(B1))

template<int OUT_MODE>
__global__ __launch_bounds__(256)
void gemm3(const bf16* __restrict__ Ah, const bf16* __restrict__ Al,
           const bf16* __restrict__ Bh, const bf16* __restrict__ Bl,
           const float* __restrict__ bias,
           float* __restrict__ Yf, bf16* __restrict__ Yh, bf16* __restrict__ Yl,
           int M, int K, int O) {
    __shared__ bf16 sAh[128][40];
    __shared__ bf16 sAl[128][40];
    __shared__ bf16 sBh[64][40];
    __shared__ bf16 sBl[64][40];

    int tid = threadIdx.x;
    int m0 = blockIdx.y * 128, n0 = blockIdx.x * 64;
    int wid = tid >> 5, lane = tid & 31;
    int wm = wid & 3, wn = wid >> 2;   // 4 x 2 warp grid

    float acc[2][4][4];
#pragma unroll
    for (int a = 0; a < 2; a++)
#pragma unroll
        for (int b = 0; b < 4; b++)
#pragma unroll
            for (int c = 0; c < 4; c++) acc[a][b][c] = 0.f;

    int lr = tid >> 2, lc = tid & 3;  // loader: row, 8-elem chunk

    for (int kk = 0; kk < K; kk += 32) {
        // A tile: 128 x 32 (hi & lo)
#pragma unroll
        for (int h = 0; h < 2; h++) {
            int r = lr + h * 64;
            size_t goff = (size_t)(m0 + r) * K + kk + lc * 8;
            *(uint4*)&sAh[r][lc * 8] = *(const uint4*)(Ah + goff);
            *(uint4*)&sAl[r][lc * 8] = *(const uint4*)(Al + goff);
        }
        // B tile: 64 x 32 (hi & lo), guard O
        {
            int wr = n0 + lr;
            uint4 vh = make_uint4(0u, 0u, 0u, 0u), vl = vh;
            if (wr < O) {
                size_t goff = (size_t)wr * K + kk + lc * 8;
                vh = *(const uint4*)(Bh + goff);
                vl = *(const uint4*)(Bl + goff);
            }
            *(uint4*)&sBh[lr][lc * 8] = vh;
            *(uint4*)&sBl[lr][lc * 8] = vl;
        }
        __syncthreads();

#pragma unroll
        for (int ks = 0; ks < 32; ks += 16) {
            unsigned ah[2][4], al[2][4], bh[2][4], bl[2][4];
#pragma unroll
            for (int mt = 0; mt < 2; mt++) {
                int row = wm * 32 + mt * 16 + (lane & 15);
                int col = ks + (lane >> 4) * 8;
                LDMX4(ah[mt], smem_u32(&sAh[row][col]));
                LDMX4(al[mt], smem_u32(&sAl[row][col]));
            }
#pragma unroll
            for (int nt = 0; nt < 2; nt++) {
                int row = wn * 32 + nt * 16 + (lane & 7) + ((lane >> 4) << 3);
                int col = ks + ((lane >> 3) & 1) * 8;
                LDMX4(bh[nt], smem_u32(&sBh[row][col]));
                LDMX4(bl[nt], smem_u32(&sBl[row][col]));
            }
#pragma unroll
            for (int mt = 0; mt < 2; mt++) {
#pragma unroll
                for (int nf = 0; nf < 4; nf++) {
                    int nt = nf >> 1, p = (nf & 1) * 2;
                    MMA16816(acc[mt][nf], ah[mt], bh[nt][p], bh[nt][p + 1]);
                    MMA16816(acc[mt][nf], ah[mt], bl[nt][p], bl[nt][p + 1]);
                    MMA16816(acc[mt][nf], al[mt], bh[nt][p], bh[nt][p + 1]);
                }
            }
        }
        __syncthreads();
    }

    // epilogue
#pragma unroll
    for (int mt = 0; mt < 2; mt++) {
#pragma unroll
        for (int nf = 0; nf < 4; nf++) {
            int row0 = m0 + wm * 32 + mt * 16 + (lane >> 2);
            int col0 = n0 + wn * 32 + nf * 8 + (lane & 3) * 2;
#pragma unroll
            for (int i = 0; i < 2; i++) {
                size_t row = row0 + i * 8;
#pragma unroll
                for (int j = 0; j < 2; j++) {
                    int col = col0 + j;
                    if (col < O) {
                        float v = acc[mt][nf][i * 2 + j] + bias[col];
                        if (OUT_MODE == 1) {
                            v = fmaxf(v, 0.f);
                            bf16 hv = __float2bfloat16(v);
                            Yh[row * O + col] = hv;
                            Yl[row * O + col] = __float2bfloat16(v - __bfloat162float(hv));
                        } else {
                            Yf[row * O + col] = v;
                        }
                    }
                }
            }
        }
    }
}

// ---------------- per-batch attention head (fp32, writes bf16 pair into concat) ----------------
__global__ __launch_bounds__(256)
void attn_kernel(const float* __restrict__ q, const float* __restrict__ k,
                 const float* __restrict__ v,
                 bf16* __restrict__ h12h, bf16* __restrict__ h12l, int head) {
    __shared__ float sq[TT * DKP];   // q, later reused for v
    __shared__ float sk[TT * DKP];
    __shared__ float ss[TT * SSP];
    int n = blockIdx.x;
    int tid = threadIdx.x;
    long base = (long)n * TT * DK;

    for (int i = tid; i < TT * DK / 4; i += 256) {
        float4 a = ((const float4*)(q + base))[i];
        float4 b = ((const float4*)(k + base))[i];
        int e = i * 4;
        int t = e / DK, d = e % DK;
        sq[t * DKP + d + 0] = a.x; sq[t * DKP + d + 1] = a.y;
        sq[t * DKP + d + 2] = a.z; sq[t * DKP + d + 3] = a.w;
        sk[t * DKP + d + 0] = b.x; sk[t * DKP + d + 1] = b.y;
        sk[t * DKP + d + 2] = b.z; sk[t * DKP + d + 3] = b.w;
    }
    __syncthreads();

    const float scale = rsqrtf((float)DK);
    for (int idx = tid; idx < TT * TT; idx += 256) {
        int t = idx / TT, s = idx % TT;
        float acc = 0.f;
#pragma unroll 8
        for (int d = 0; d < DK; d++) acc += sq[t * DKP + d] * sk[s * DKP + d];
        ss[t * SSP + s] = acc * scale;
    }
    __syncthreads();

    for (int i = tid; i < TT * DK / 4; i += 256) {
        float4 a = ((const float4*)(v + base))[i];
        int e = i * 4;
        int t = e / DK, d = e % DK;
        sq[t * DKP + d + 0] = a.x; sq[t * DKP + d + 1] = a.y;
        sq[t * DKP + d + 2] = a.z; sq[t * DKP + d + 3] = a.w;
    }
    int wid = tid >> 5, lane = tid & 31;
    for (int t = wid; t < TT; t += 8) {
        float m = -1e30f;
        for (int s = lane; s < TT; s += 32) m = fmaxf(m, ss[t * SSP + s]);
#pragma unroll
        for (int o = 16; o; o >>= 1) m = fmaxf(m, __shfl_xor_sync(0xffffffffu, m, o));
        float sum = 0.f;
        for (int s = lane; s < TT; s += 32) {
            float e = __expf(ss[t * SSP + s] - m);
            ss[t * SSP + s] = e;
            sum += e;
        }
#pragma unroll
        for (int o = 16; o; o >>= 1) sum += __shfl_xor_sync(0xffffffffu, sum, o);
        float inv = 1.f / sum;
        for (int s = lane; s < TT; s += 32) ss[t * SSP + s] *= inv;
    }
    __syncthreads();

    for (int idx = tid; idx < TT * DK; idx += 256) {
        int t = idx / DK, d = idx % DK;
        float acc = 0.f;
#pragma unroll 43
        for (int s = 0; s < TT; s++) acc += ss[t * SSP + s] * sq[s * DKP + d];
        size_t o = (size_t)(n * TT + t) * (2 * DK) + head * DK + d;
        split_store(acc, h12h, h12l, o);
    }
}

// ---------------- add residual + LayerNorm (fp32 out + bf16 pair out) ----------------
__global__ __launch_bounds__(128)
void add_ln_kernel(const float* __restrict__ y, const float* __restrict__ r,
                   const float* __restrict__ g, const float* __restrict__ b,
                   float* __restrict__ o, bf16* __restrict__ oh, bf16* __restrict__ ol) {
    long row = blockIdx.x;
    int h = threadIdx.x;
    __shared__ float red[8];
    float v = y[row * HD + h] + r[row * HD + h];
    float s = v;
#pragma unroll
    for (int off = 16; off; off >>= 1) s += __shfl_xor_sync(0xffffffffu, s, off);
    int wid = h >> 5, lane = h & 31;
    if (!lane) red[wid] = s;
    __syncthreads();
    float mean = (red[0] + red[1] + red[2] + red[3]) * (1.f / HD);
    float d = v - mean;
    float s2 = d * d;
#pragma unroll
    for (int off = 16; off; off >>= 1) s2 += __shfl_xor_sync(0xffffffffu, s2, off);
    if (!lane) red[4 + wid] = s2;
    __syncthreads();
    float var = (red[4] + red[5] + red[6] + red[7]) * (1.f / HD);
    float out = d * rsqrtf(var + LNEPS) * g[h] + b[h];
    o[row * HD + h] = out;
    split_store(out, oh, ol, row * HD + h);
}

// ---------------- host launch ----------------
extern "C" void kernel_launch(void* const* d_in, const int* in_sizes, int n_in,
                              void* d_out, int out_size) {
    const int*   inputs = (const int*)  d_in[0];
    const float* emb    = (const float*)d_in[1];
    const float* pos    = (const float*)d_in[2];
    const float* Wk1 = (const float*)d_in[3],  *bk1 = (const float*)d_in[4];
    const float* Wv1 = (const float*)d_in[5],  *bv1 = (const float*)d_in[6];
    const float* Wq1 = (const float*)d_in[7],  *bq1 = (const float*)d_in[8];
    const float* Wk2 = (const float*)d_in[9],  *bk2 = (const float*)d_in[10];
    const float* Wv2 = (const float*)d_in[11], *bv2 = (const float*)d_in[12];
    const float* Wq2 = (const float*)d_in[13], *bq2 = (const float*)d_in[14];
    const float* Wproj = (const float*)d_in[15], *bproj = (const float*)d_in[16];
    const float* gmh   = (const float*)d_in[17], *bmh   = (const float*)d_in[18];
    const float* Wff1  = (const float*)d_in[19], *bff1  = (const float*)d_in[20];
    const float* Wff2  = (const float*)d_in[21], *bff2  = (const float*)d_in[22];
    const float* gff   = (const float*)d_in[23], *bffb  = (const float*)d_in[24];
    const float* Wfin  = (const float*)d_in[25], *bfin  = (const float*)d_in[26];
    float* out = (float*)d_out;

    float *x0, *q1, *k1, *v1, *q2, *k2, *v2, *mho, *x1, *ff2, *x2;
    bf16 *x0h, *x0l, *h12h, *h12l, *x1h, *x1l, *ffhh, *ffhl, *x2h, *x2l, *wh, *wl;
    cudaGetSymbolAddress((void**)&x0,   g_x0);
    cudaGetSymbolAddress((void**)&x0h,  g_x0h);
    cudaGetSymbolAddress((void**)&x0l,  g_x0l);
    cudaGetSymbolAddress((void**)&q1,   g_q1);
    cudaGetSymbolAddress((void**)&k1,   g_k1);
    cudaGetSymbolAddress((void**)&v1,   g_v1);
    cudaGetSymbolAddress((void**)&q2,   g_q2);
    cudaGetSymbolAddress((void**)&k2,   g_k2);
    cudaGetSymbolAddress((void**)&v2,   g_v2);
    cudaGetSymbolAddress((void**)&h12h, g_h12h);
    cudaGetSymbolAddress((void**)&h12l, g_h12l);
    cudaGetSymbolAddress((void**)&mho,  g_mho);
    cudaGetSymbolAddress((void**)&x1,   g_x1);
    cudaGetSymbolAddress((void**)&x1h,  g_x1h);
    cudaGetSymbolAddress((void**)&x1l,  g_x1l);
    cudaGetSymbolAddress((void**)&ffhh, g_ffhh);
    cudaGetSymbolAddress((void**)&ffhl, g_ffhl);
    cudaGetSymbolAddress((void**)&ff2,  g_ff2);
    cudaGetSymbolAddress((void**)&x2,   g_x2);
    cudaGetSymbolAddress((void**)&x2h,  g_x2h);
    cudaGetSymbolAddress((void**)&x2l,  g_x2l);
    cudaGetSymbolAddress((void**)&wh,   g_wh);
    cudaGetSymbolAddress((void**)&wl,   g_wl);

    const int MB = NTOK / 128;  // 172

    // weight conversions (cheap; graph-capturable kernels)
    convert_kernel<<<(DK*HD + 255) / 256, 256>>>(Wk1, wh + OFF_K1, wl + OFF_K1, DK * HD);
    convert_kernel<<<(DK*HD + 255) / 256, 256>>>(Wv1, wh + OFF_V1, wl + OFF_V1, DK * HD);
    convert_kernel<<<(DK*HD + 255) / 256, 256>>>(Wq1, wh + OFF_Q1, wl + OFF_Q1, DK * HD);
    convert_kernel<<<(DK*HD + 255) / 256, 256>>>(Wk2, wh + OFF_K2, wl + OFF_K2, DK * HD);
    convert_kernel<<<(DK*HD + 255) / 256, 256>>>(Wv2, wh + OFF_V2, wl + OFF_V2, DK * HD);
    convert_kernel<<<(DK*HD + 255) / 256, 256>>>(Wq2, wh + OFF_Q2, wl + OFF_Q2, DK * HD);
    convert_kernel<<<(HD*2*DK + 255) / 256, 256>>>(Wproj, wh + OFF_PROJ, wl + OFF_PROJ, HD * 2 * DK);
    convert_kernel<<<(DFF*HD + 255) / 256, 256>>>(Wff1, wh + OFF_FF1, wl + OFF_FF1, DFF * HD);
    convert_kernel<<<(HD*DFF + 255) / 256, 256>>>(Wff2, wh + OFF_FF2, wl + OFF_FF2, HD * DFF);
    convert_kernel<<<(OUTV*HD + 255) / 256, 256>>>(Wfin, wh + OFF_FIN, wl + OFF_FIN, OUTV * HD);

    embed_kernel<<<(NTOK * 32 + 255) / 256, 256>>>(inputs, emb, pos, x0, x0h, x0l);

    dim3 gqkv(2, MB);
    gemm3<0><<<gqkv, 256>>>(x0h, x0l, wh + OFF_Q1, wl + OFF_Q1, bq1, q1, nullptr, nullptr, NTOK, HD, DK);
    gemm3<0><<<gqkv, 256>>>(x0h, x0l, wh + OFF_K1, wl + OFF_K1, bk1, k1, nullptr, nullptr, NTOK, HD, DK);
    gemm3<0><<<gqkv, 256>>>(x0h, x0l, wh + OFF_V1, wl + OFF_V1, bv1, v1, nullptr, nullptr, NTOK, HD, DK);
    gemm3<0><<<gqkv, 256>>>(x0h, x0l, wh + OFF_Q2, wl + OFF_Q2, bq2, q2, nullptr, nullptr, NTOK, HD, DK);
    gemm3<0><<<gqkv, 256>>>(x0h, x0l, wh + OFF_K2, wl + OFF_K2, bk2, k2, nullptr, nullptr, NTOK, HD, DK);
    gemm3<0><<<gqkv, 256>>>(x0h, x0l, wh + OFF_V2, wl + OFF_V2, bv2, v2, nullptr, nullptr, NTOK, HD, DK);

    attn_kernel<<<NB, 256>>>(q1, k1, v1, h12h, h12l, 0);
    attn_kernel<<<NB, 256>>>(q2, k2, v2, h12h, h12l, 1);

    gemm3<0><<<dim3(2, MB), 256>>>(h12h, h12l, wh + OFF_PROJ, wl + OFF_PROJ, bproj, mho, nullptr, nullptr, NTOK, 2 * DK, HD);
    add_ln_kernel<<<NTOK, 128>>>(mho, x0, gmh, bmh, x1, x1h, x1l);

    gemm3<1><<<dim3(DFF / 64, MB), 256>>>(x1h, x1l, wh + OFF_FF1, wl + OFF_FF1, bff1, nullptr, ffhh, ffhl, NTOK, HD, DFF);
    gemm3<0><<<dim3(2, MB), 256>>>(ffhh, ffhl, wh + OFF_FF2, wl + OFF_FF2, bff2, ff2, nullptr, nullptr, NTOK, DFF, HD);
    add_ln_kernel<<<NTOK, 128>>>(ff2, x1, gff, bffb, x2, x2h, x2l);

    gemm3<0><<<dim3(OUTV / 64, MB), 256>>>(x2h, x2l, wh + OFF_FIN, wl + OFF_FIN, bfin, out, nullptr, nullptr, NTOK, HD, OUTV);
}